// round 16
// baseline (speedup 1.0000x reference)
#include <cuda_runtime.h>
#include <cuda_fp16.h>
#include <cstdint>
#include <math.h>

#define MAX_NODES 200000
#define GDIM 128

// ---------------------------------------------------------------------------
// Pre-transposed fp16 weights: Wt[n][k] = W[k][n]  (__device__ globals)
// ---------------------------------------------------------------------------
__device__ __align__(16) __half g_Wi1t[512 * 256];
__device__ __align__(16) __half g_Wi2t[128 * 512];
__device__ __align__(16) __half g_Wj1t[512 * 128];
__device__ __align__(16) __half g_Wj2t[128 * 512];

// ---------------------------------------------------------------------------
__device__ __forceinline__ uint32_t smem_to_u32(const void* p) {
    uint32_t a;
    asm("{ .reg .u64 t; cvta.to.shared.u64 t, %1; cvt.u32.u64 %0, t; }" : "=r"(a) : "l"(p));
    return a;
}
#define SWZ64(o) ((o) ^ (((o) >> 3) & 0x30))

__device__ __forceinline__ void ldmatrix_x4(uint32_t& r0, uint32_t& r1,
                                            uint32_t& r2, uint32_t& r3, uint32_t addr) {
    asm volatile("ldmatrix.sync.aligned.m8n8.x4.shared.b16 {%0,%1,%2,%3}, [%4];"
                 : "=r"(r0), "=r"(r1), "=r"(r2), "=r"(r3) : "r"(addr));
}

__device__ __forceinline__ void mma_fp16(float* d, uint32_t a0, uint32_t a1,
                                         uint32_t a2, uint32_t a3,
                                         uint32_t b0, uint32_t b1) {
    asm volatile(
        "mma.sync.aligned.m16n8k16.row.col.f32.f16.f16.f32 "
        "{%0,%1,%2,%3}, {%4,%5,%6,%7}, {%8,%9}, {%0,%1,%2,%3};"
        : "+f"(d[0]), "+f"(d[1]), "+f"(d[2]), "+f"(d[3])
        : "r"(a0), "r"(a1), "r"(a2), "r"(a3), "r"(b0), "r"(b1));
}

__device__ __forceinline__ void cp16(uint32_t saddr, const void* g) {
    asm volatile("cp.async.ca.shared.global [%0], [%1], 16;"
                 :: "r"(saddr), "l"(g));
}
#define CP_COMMIT()  asm volatile("cp.async.commit_group;" ::: "memory")
#define CP_WAIT(N)   asm volatile("cp.async.wait_group %0;" :: "n"(N) : "memory")

// ---------------------------------------------------------------------------
// Prep: zero output + all 4 weight transposes in ONE launch.
// ---------------------------------------------------------------------------
__global__ void prep_kernel(const float* __restrict__ Wi1, const float* __restrict__ Wi2,
                            const float* __restrict__ Wj1, const float* __restrict__ Wj2,
                            __half* __restrict__ Wi1t, __half* __restrict__ Wi2t,
                            __half* __restrict__ Wj1t, __half* __restrict__ Wj2t,
                            float* __restrict__ R, int rn)
{
    int i = blockIdx.x * blockDim.x + threadIdx.x;
    if (i < rn) R[i] = 0.0f;
    if (i < 256 * 512) {
        int k = i / 512, n = i % 512;
        Wi1t[(size_t)n * 256 + k] = __float2half_rn(Wi1[i]);
    }
    if (i < 512 * 128) {
        int k = i / 128, n = i % 128;
        Wi2t[(size_t)n * 512 + k] = __float2half_rn(Wi2[i]);
        Wj2t[(size_t)n * 512 + k] = __float2half_rn(Wj2[i]);
        int k2 = i / 512, n2 = i % 512;
        Wj1t[(size_t)n2 * 128 + k2] = __float2half_rn(Wj1[i]);
    }
}

// ---------------------------------------------------------------------------
// Mega-kernel: one CTA (512 threads, 16 warps) per 128-row block.
//   X  = fp16([h_T | h_0])                       smem, 8 chunks (h_T = 0..3)
//   H  = relu(X * Wi1^T + bi1)                   smem, 16 chunks
//   Zi = H * Wi2^T + bi2 ; gate = sigmoid(Zi)    registers (32 fp32/thread)
//   H  = relu(h_T * Wj1^T + bj1)                 smem (overwrite)
//   Zj = H * Wj2^T + bj2 ; v = gate * Zj
//   R += segmented_sum(v) over sorted gidx       sparse atomics
// 16 warps (4M x 4N), warp tile 32x32, K-chunk 32, 3-stage cp.async weights.
// ---------------------------------------------------------------------------
#define SMEM_DYN (1024 + (8 + 16 + 3) * 8192)   // 222208

__global__ __launch_bounds__(512, 1)
void mega_mlp(const float* __restrict__ hT, const float* __restrict__ h0,
              const __half* __restrict__ Wi1t, const float* __restrict__ bi1,
              const __half* __restrict__ Wi2t, const float* __restrict__ bi2,
              const __half* __restrict__ Wj1t, const float* __restrict__ bj1,
              const __half* __restrict__ Wj2t, const float* __restrict__ bj2,
              const int* __restrict__ gidx, float* __restrict__ Rout, int M)
{
    extern __shared__ char smem_raw[];
    const uint32_t sb = smem_to_u32(smem_raw);
    const uint32_t base = (sb + 1023) & ~1023u;
    char* basep = smem_raw + (base - sb);

    const uint32_t Xa = base;                 // 8 chunks: [h_T(4) | h_0(4)]
    const uint32_t Ha = base + 8 * 8192;      // 16 chunks
    const uint32_t Sa = Ha + 16 * 8192;       // 3 weight stages
    const int Hoff = 8 * 8192;

    const int tid  = threadIdx.x;
    const int wid  = tid >> 5;
    const int lane = tid & 31;
    const int wm = wid & 3;                   // 4 warp-rows of 32
    const int wn = wid >> 2;                  // 4 warp-cols of 32
    const int m0 = blockIdx.x * 128;
    const int lr = lane & 7;
    const int q  = lane >> 3;
    const int g  = lane >> 2, tig = lane & 3;

    // ---------------- X staging: fp32 -> fp16, swizzled chunks ----------------
#pragma unroll
    for (int i = 0; i < 16; i++) {           // 128 rows x 64 float4 = 8192
        int idx = tid + i * 512;
        int r = idx >> 6;
        int col = (idx & 63) << 2;           // 0..252
        const float* src = (col < 128) ? hT : h0;
        int kb = (col < 128) ? col : col - 128;
        float4 v = make_float4(0.f, 0.f, 0.f, 0.f);
        if (m0 + r < M)
            v = *reinterpret_cast<const float4*>(src + (size_t)(m0 + r) * 128 + kb);
        __half2 p0 = __halves2half2(__float2half_rn(v.x), __float2half_rn(v.y));
        __half2 p1 = __halves2half2(__float2half_rn(v.z), __float2half_rn(v.w));
        int ch = col >> 5, cb = col & 31;
        uint32_t o = SWZ64((r << 6) + (cb << 1));
        *reinterpret_cast<__half2*>(basep + ch * 8192 + o)     = p0;
        *reinterpret_cast<__half2*>(basep + ch * 8192 + o + 4) = p1;
    }

    float acc[2][4][4];
    float gate[2][4][4];

    auto load_B = [&](const __half* Bsrc, int ldb, int nb0, int kc, int s) {
        const int k0 = kc << 5;
        // 512 x 16B = 8KB stage, exactly one cp per thread
        int r = tid >> 2, c16 = tid & 3;
        cp16(Sa + s * 8192 + SWZ64((r << 6) + (c16 << 4)),
             Bsrc + (size_t)(nb0 + r) * ldb + k0 + (c16 << 3));
        CP_COMMIT();
    };

    auto compute = [&](uint32_t As, uint32_t Bs) {
#pragma unroll
        for (int s = 0; s < 2; s++) {
            const int bc = s << 5;
            uint32_t bf[8];
#pragma unroll
            for (int p = 0; p < 2; p++) {
                int nrow = (wn << 5) + (p << 4) + ((q >> 1) << 3) + lr;
                uint32_t o = SWZ64((nrow << 6) + bc + ((q & 1) << 4));
                ldmatrix_x4(bf[p * 4 + 0], bf[p * 4 + 1], bf[p * 4 + 2], bf[p * 4 + 3], Bs + o);
            }
#pragma unroll
            for (int mt = 0; mt < 2; mt++) {
                int mrow = (wm << 5) + (mt << 4) + ((q & 1) << 3) + lr;
                uint32_t o = SWZ64((mrow << 6) + bc + ((q >> 1) << 4));
                uint32_t a0, a1, a2, a3;
                ldmatrix_x4(a0, a1, a2, a3, As + o);
#pragma unroll
                for (int nt = 0; nt < 4; nt++) {
                    int bi = (nt >> 1) * 4 + (nt & 1) * 2;
                    mma_fp16(acc[mt][nt], a0, a1, a2, a3, bf[bi], bf[bi + 1]);
                }
            }
        }
    };

    // pipelined GEMM over KC chunks: A resident at Aa, B streamed
    auto run_gemm = [&](uint32_t Aa, const __half* Bsrc, int ldb, int nb0, int KC) {
#pragma unroll
        for (int a = 0; a < 2; a++)
#pragma unroll
            for (int b = 0; b < 4; b++)
#pragma unroll
                for (int d = 0; d < 4; d++) acc[a][b][d] = 0.0f;
        __syncthreads();
        load_B(Bsrc, ldb, nb0, 0, 0);
        if (KC > 1) load_B(Bsrc, ldb, nb0, 1, 1);
        for (int kc = 0; kc < KC; kc++) {
            if (kc + 1 < KC) { CP_WAIT(1); } else { CP_WAIT(0); }
            __syncthreads();
            if (kc + 2 < KC) load_B(Bsrc, ldb, nb0, kc + 2, (kc + 2) % 3);
            compute(Aa + kc * 8192, Sa + (kc % 3) * 8192);
        }
    };

    // layer-1 (hidden): H = relu(A * B1^T + b1) over 4 n-chunks of 128
    auto layer1 = [&](const __half* B1, const float* b1, int KC1) {
#pragma unroll 1
        for (int nc = 0; nc < 4; nc++) {
            run_gemm(Xa, B1, KC1 << 5, nc * 128, KC1);
#pragma unroll
            for (int mt = 0; mt < 2; mt++) {
#pragma unroll
                for (int hf = 0; hf < 2; hf++) {
                    int lrow = (wm << 5) + (mt << 4) + g + (hf << 3);
#pragma unroll
                    for (int nt = 0; nt < 4; nt++) {
                        int col = nc * 128 + (wn << 5) + (nt << 3) + (tig << 1);
                        float v0 = fmaxf(acc[mt][nt][hf * 2 + 0] + __ldg(b1 + col), 0.0f);
                        float v1 = fmaxf(acc[mt][nt][hf * 2 + 1] + __ldg(b1 + col + 1), 0.0f);
                        int hc = col >> 5, cb = col & 31;
                        uint32_t o = SWZ64((lrow << 6) + (cb << 1));
                        *reinterpret_cast<__half2*>(basep + Hoff + hc * 8192 + o) =
                            __halves2half2(__float2half_rn(v0), __float2half_rn(v1));
                    }
                }
            }
        }
    };

    // ============ i-net ============
    layer1(Wi1t, bi1, 8);                       // H = relu(X Wi1 + bi1), K=256
    run_gemm(Ha, Wi2t, 512, 0, 16);             // Zi = H Wi2
#pragma unroll
    for (int mt = 0; mt < 2; mt++)
#pragma unroll
        for (int nt = 0; nt < 4; nt++)
#pragma unroll
            for (int d = 0; d < 4; d++) {
                int col = (wn << 5) + (nt << 3) + (tig << 1) + (d & 1);
                float z = acc[mt][nt][d] + __ldg(bi2 + col);
                gate[mt][nt][d] = 1.0f / (1.0f + __expf(-z));
            }

    // ============ j-net ============
    layer1(Wj1t, bj1, 4);                       // H = relu(h_T Wj1 + bj1), K=128
    run_gemm(Ha, Wj2t, 512, 0, 16);             // Zj = H Wj2

    // ============ gated product + segmented reduction ============
    __syncthreads();                            // H region dead -> Dts
    float* Dts = reinterpret_cast<float*>(basep + Hoff);
#pragma unroll
    for (int mt = 0; mt < 2; mt++) {
#pragma unroll
        for (int hf = 0; hf < 2; hf++) {
            int lrow = (wm << 5) + (mt << 4) + g + (hf << 3);
            if (m0 + lrow >= M) continue;
#pragma unroll
            for (int nt = 0; nt < 4; nt++) {
                int col = (wn << 5) + (nt << 3) + (tig << 1);
                float v0 = (acc[mt][nt][hf * 2 + 0] + __ldg(bj2 + col))     * gate[mt][nt][hf * 2 + 0];
                float v1 = (acc[mt][nt][hf * 2 + 1] + __ldg(bj2 + col + 1)) * gate[mt][nt][hf * 2 + 1];
                *reinterpret_cast<float2*>(Dts + lrow * 132 + col) = make_float2(v0, v1);
            }
        }
    }
    __syncthreads();

    if (tid < 256) {
        const int tx = tid & 15, ty = tid >> 4;
        const int tm = ty * 8, tn = tx * 8;
        int cur = -1;
        float run[8];
#pragma unroll
        for (int j = 0; j < 8; j++) run[j] = 0.0f;
        for (int i = 0; i < 8; i++) {
            int r = m0 + tm + i;
            if (r >= M) break;
            int gg = gidx[r];
            if (gg != cur) {
                if (cur >= 0) {
#pragma unroll
                    for (int j = 0; j < 8; j++)
                        atomicAdd(&Rout[(size_t)cur * GDIM + tn + j], run[j]);
                }
                cur = gg;
#pragma unroll
                for (int j = 0; j < 8; j++) run[j] = 0.0f;
            }
#pragma unroll
            for (int j = 0; j < 8; j++)
                run[j] += Dts[(tm + i) * 132 + tn + j];
        }
        if (cur >= 0) {
#pragma unroll
            for (int j = 0; j < 8; j++)
                atomicAdd(&Rout[(size_t)cur * GDIM + tn + j], run[j]);
        }
    }
}

// ---------------------------------------------------------------------------
extern "C" void kernel_launch(void* const* d_in, const int* in_sizes, int n_in,
                              void* d_out, int out_size)
{
    const float* h_T  = (const float*)d_in[0];
    const float* h_0  = (const float*)d_in[1];
    const int*   gidx = (const int*)d_in[2];     // int32 (JAX x64 disabled)
    const float* Wi1  = (const float*)d_in[3];
    const float* bi1  = (const float*)d_in[4];
    const float* Wi2  = (const float*)d_in[5];
    const float* bi2  = (const float*)d_in[6];
    const float* Wj1  = (const float*)d_in[7];
    const float* bj1  = (const float*)d_in[8];
    const float* Wj2  = (const float*)d_in[9];
    const float* bj2  = (const float*)d_in[10];
    float* R = (float*)d_out;

    const int M = in_sizes[0] / 128;
    const int mt = (M + 127) / 128;

    __half *Wi1t, *Wi2t, *Wj1t, *Wj2t;
    cudaGetSymbolAddress((void**)&Wi1t, g_Wi1t);
    cudaGetSymbolAddress((void**)&Wi2t, g_Wi2t);
    cudaGetSymbolAddress((void**)&Wj1t, g_Wj1t);
    cudaGetSymbolAddress((void**)&Wj2t, g_Wj2t);

    cudaFuncSetAttribute(mega_mlp, cudaFuncAttributeMaxDynamicSharedMemorySize, SMEM_DYN);

    // single prep launch: zero R + all weight transposes
    prep_kernel<<<(256 * 512 + 255) / 256, 256>>>(Wi1, Wi2, Wj1, Wj2,
                                                  Wi1t, Wi2t, Wj1t, Wj2t, R, out_size);

    mega_mlp<<<mt, 512, SMEM_DYN>>>(h_T, h_0,
                                    Wi1t, bi1, Wi2t, bi2,
                                    Wj1t, bj1, Wj2t, bj2,
                                    gidx, R, M);
}